// round 11
// baseline (speedup 1.0000x reference)
#include <cuda_runtime.h>
#include <cstdint>

// Problem constants
#define BB 4
#define TT 4096
#define DD 1024
#define HDIM 64
#define MTOT (BB*TT)   // 16384 rows

// Scratch: Q, K, V row-major [b*T, 64]; Q pre-scaled by 1/8; all tf32-rounded.
__device__ float g_QKV[3][(size_t)MTOT * HDIM];

// ---------------------------- helpers --------------------------------------
__device__ __forceinline__ float to_tf32(float x) {
    uint32_t u;
    asm("cvt.rna.tf32.f32 %0, %1;" : "=r"(u) : "f"(x));
    return __uint_as_float(u);
}

__device__ __forceinline__ uint32_t smem_u32(const void* p) {
    uint32_t a;
    asm("{ .reg .u64 t; cvta.to.shared.u64 t, %1; cvt.u32.u64 %0, t; }"
        : "=r"(a) : "l"(p));
    return a;
}

// cp.async 16B, L2-cached (cg). sm_80+ -> safe on the sm_103 family target.
__device__ __forceinline__ void cp16(uint32_t dst, const void* src) {
    asm volatile("cp.async.cg.shared.global [%0], [%1], 16;"
                 :: "r"(dst), "l"(src) : "memory");
}
#define CP_COMMIT() asm volatile("cp.async.commit_group;" ::: "memory")
#define CP_WAIT0()  asm volatile("cp.async.wait_group 0;" ::: "memory")

// m16n8k8 tf32 mma, D += A*B (accumulate in place)
__device__ __forceinline__ void mma8(float* d, const uint32_t* a, const uint32_t* b) {
    asm volatile(
        "mma.sync.aligned.m16n8k8.row.col.f32.tf32.tf32.f32 "
        "{%0,%1,%2,%3}, {%4,%5,%6,%7}, {%8,%9}, {%0,%1,%2,%3};"
        : "+f"(d[0]), "+f"(d[1]), "+f"(d[2]), "+f"(d[3])
        : "r"(a[0]), "r"(a[1]), "r"(a[2]), "r"(a[3]), "r"(b[0]), "r"(b[1]));
}

// ---------------------------------------------------------------------------
// Projection via tensor cores (unchanged from R6): out[m,0:192] = x @ [wq|wk|wv]^T
// ---------------------------------------------------------------------------
#define PKC 32
#define PSTRIDE 36
#define PXSZ (128 * PSTRIDE)
#define PWSZ (192 * PSTRIDE)
#define PBUF (PXSZ + PWSZ)
#define PROJ_SMEM (2 * PBUF * 4)         // 92160 bytes

__global__ __launch_bounds__(256, 1) void proj_mma_kernel(
    const float* __restrict__ x,
    const float* __restrict__ wq,
    const float* __restrict__ wk,
    const float* __restrict__ wv)
{
    extern __shared__ __align__(16) float psm[];

    const int tid  = threadIdx.x;
    const int wid  = tid >> 5;
    const int lane = tid & 31;
    const int wm   = wid >> 1;
    const int wn   = wid & 1;
    const int row  = lane >> 2;
    const int col  = lane & 3;
    const int m0   = blockIdx.x * 128;

    const float* xsrc[4];
    const float* wsrc[6];
    int xdst[4], wdst[6];
#pragma unroll
    for (int i = 0; i < 4; i++) {
        int idx = tid + i * 256;
        int r = idx >> 3, q = idx & 7;
        xsrc[i] = &x[(size_t)(m0 + r) * DD + q * 4];
        xdst[i] = r * PSTRIDE + q * 4;
    }
#pragma unroll
    for (int i = 0; i < 6; i++) {
        int idx = tid + i * 256;
        int r = idx >> 3, q = idx & 7;
        const float* wbase = (r < 64) ? &wq[(size_t)r * DD]
                           : (r < 128) ? &wk[(size_t)(r - 64) * DD]
                                       : &wv[(size_t)(r - 128) * DD];
        wsrc[i] = wbase + q * 4;
        wdst[i] = r * PSTRIDE + q * 4;
    }

    float acc[2][12][4];
#pragma unroll
    for (int mf = 0; mf < 2; mf++)
#pragma unroll
        for (int nf = 0; nf < 12; nf++)
#pragma unroll
            for (int j = 0; j < 4; j++) acc[mf][nf][j] = 0.0f;

    float4 xr[4], wr[6];
#pragma unroll
    for (int i = 0; i < 4; i++) xr[i] = *reinterpret_cast<const float4*>(xsrc[i]);
#pragma unroll
    for (int i = 0; i < 6; i++) wr[i] = *reinterpret_cast<const float4*>(wsrc[i]);

    for (int ci = 0; ci < DD / PKC; ci++) {
        float* Xb = psm + (ci & 1) * PBUF;
        float* Wb = Xb + PXSZ;

#pragma unroll
        for (int i = 0; i < 4; i++) {
            float4 v = xr[i];
            float4 t = make_float4(to_tf32(v.x), to_tf32(v.y), to_tf32(v.z), to_tf32(v.w));
            *reinterpret_cast<float4*>(&Xb[xdst[i]]) = t;
        }
#pragma unroll
        for (int i = 0; i < 6; i++) {
            float4 v = wr[i];
            float4 t = make_float4(to_tf32(v.x), to_tf32(v.y), to_tf32(v.z), to_tf32(v.w));
            *reinterpret_cast<float4*>(&Wb[wdst[i]]) = t;
        }
        __syncthreads();

        if (ci + 1 < DD / PKC) {
            const int kb = (ci + 1) * PKC;
#pragma unroll
            for (int i = 0; i < 4; i++)
                xr[i] = *reinterpret_cast<const float4*>(xsrc[i] + kb);
#pragma unroll
            for (int i = 0; i < 6; i++)
                wr[i] = *reinterpret_cast<const float4*>(wsrc[i] + kb);
        }

#pragma unroll
        for (int ks = 0; ks < 4; ks++) {
            uint32_t a[2][4];
#pragma unroll
            for (int mf = 0; mf < 2; mf++) {
                const float* ab = &Xb[(wm * 32 + mf * 16 + row) * PSTRIDE + ks * 8 + col];
                a[mf][0] = __float_as_uint(ab[0]);
                a[mf][1] = __float_as_uint(ab[8 * PSTRIDE]);
                a[mf][2] = __float_as_uint(ab[4]);
                a[mf][3] = __float_as_uint(ab[8 * PSTRIDE + 4]);
            }
#pragma unroll
            for (int nf = 0; nf < 12; nf++) {
                const float* bbp = &Wb[(wn * 96 + nf * 8 + row) * PSTRIDE + ks * 8 + col];
                uint32_t bb[2];
                bb[0] = __float_as_uint(bbp[0]);
                bb[1] = __float_as_uint(bbp[4]);
                mma8(acc[0][nf], a[0], bb);
                mma8(acc[1][nf], a[1], bb);
            }
        }
    }

#pragma unroll
    for (int mf = 0; mf < 2; mf++) {
#pragma unroll
        for (int i = 0; i < 2; i++) {
            const int m = m0 + wm * 32 + mf * 16 + 8 * i + row;
#pragma unroll
            for (int nf = 0; nf < 12; nf++) {
                const int cg = wn * 96 + nf * 8 + 2 * col;
                const int which = cg >> 6;
                const int n = cg & 63;
                const float scale = (which == 0) ? 0.125f : 1.0f;
                float2 v = make_float2(to_tf32(acc[mf][nf][2 * i] * scale),
                                       to_tf32(acc[mf][nf][2 * i + 1] * scale));
                *reinterpret_cast<float2*>(&g_QKV[which][(size_t)m * HDIM + n]) = v;
            }
        }
    }
}

// ---------------------------------------------------------------------------
// Tensor-core attention: R9's proven cp.async pipeline (K single-buffered,
// V double-buffered, 2 syncs/chunk, PSTR2=132), retiled to 512 threads /
// 16 warps (4m x 4n) for 4 warps/SMSP of latency hiding.
//
//   S  = Q K^T : warp tile 32x32 (2 mf x 4 nf), K=64  -> sacc 32 regs
//   PV = P V   : warp tile 32x16 (2 mf x 2 nf), K=128 -> oacc 16 regs
// smem (floats): Qs 128*68 | Ks 128*68 | Vs[2] 128*72 | Ps 128*132 | ls 4*128
//   total 53248 floats = 212992 bytes.
// ---------------------------------------------------------------------------
#define BM 128
#define BN 128
#define NCH (TT / BN)
#define QSTR 68
#define KSTR 68
#define VSTR 72
#define PSTR2 132
#define VBUF (128 * VSTR)

#define OFF_Q  0
#define OFF_K  (OFF_Q + 128 * QSTR)            //  8704
#define OFF_V  (OFF_K + 128 * KSTR)            // 17408 (buf b at + b*VBUF)
#define OFF_P  (OFF_V + 2 * VBUF)              // 35840
#define OFF_L  (OFF_P + 128 * PSTR2)           // 52736
#define ATTN_SMEM ((OFF_L + 512) * 4)          // 212992 bytes

__global__ __launch_bounds__(512, 1) void attn_mma_kernel(float* __restrict__ out)
{
    extern __shared__ __align__(16) float sm[];
    float* Qs = sm + OFF_Q;
    float* Ps = sm + OFF_P;
    float* ls = sm + OFF_L;
    const uint32_t sb = smem_u32(sm);

    const int tid  = threadIdx.x;
    const int wid  = tid >> 5;
    const int lane = tid & 31;
    const int wm   = wid >> 2;          // 0..3 : 32-row group
    const int wn   = wid & 3;           // 0..3 : n-quarter
    const int row  = lane >> 2;         // 0..7
    const int col  = lane & 3;          // 0..3

    const int b  = blockIdx.y;
    const int t0 = blockIdx.x * BM;
    const float* Q  = g_QKV[0];
    const float* Kg = g_QKV[1];
    const float* Vg = g_QKV[2];
    const size_t base = (size_t)b * TT * HDIM;

    // Staging geometry: 512 threads; rb = tid>>4 (0..31), cc fixed; rows rb+32*it.
    const int rb = tid >> 4;
    const int cc = (tid & 15) << 2;

    // Load Q tile once (plain LDG/STS): 128 x 64, 4 float4 per thread.
#pragma unroll
    for (int it = 0; it < 4; it++) {
        int r = rb + 32 * it;
        float4 v = *reinterpret_cast<const float4*>(&Q[base + (size_t)(t0 + r) * HDIM + cc]);
        *reinterpret_cast<float4*>(&Qs[r * QSTR + cc]) = v;
    }

    // Issue chunk 0 K/V copies (K -> single buffer, V -> buffer 0).
#pragma unroll
    for (int it = 0; it < 4; it++) {
        int r = rb + 32 * it;
        cp16(sb + (uint32_t)(OFF_K + r * KSTR + cc) * 4, &Kg[base + (size_t)r * HDIM + cc]);
        cp16(sb + (uint32_t)(OFF_V + r * VSTR + cc) * 4, &Vg[base + (size_t)r * HDIM + cc]);
    }
    CP_COMMIT();

    float oacc[2][2][4];
    float lsum[2][2];
#pragma unroll
    for (int mf = 0; mf < 2; mf++) {
        lsum[mf][0] = 0.0f; lsum[mf][1] = 0.0f;
#pragma unroll
        for (int nf = 0; nf < 2; nf++)
#pragma unroll
            for (int j = 0; j < 4; j++) oacc[mf][nf][j] = 0.0f;
    }

    for (int ci = 0; ci < NCH; ci++) {
        const int cur = ci & 1;
        const float* Ks = sm + OFF_K;
        const float* Vs = sm + OFF_V + cur * VBUF;

        CP_WAIT0();
        __syncthreads();   // chunk ci K/V resident & visible; PV(ci-1) reads done

        // ---- S = Q K^T : M128 N128 K64, warp tile 32x32 ----
        float sacc[2][4][4];
#pragma unroll
        for (int mf = 0; mf < 2; mf++)
#pragma unroll
            for (int nf = 0; nf < 4; nf++)
#pragma unroll
                for (int j = 0; j < 4; j++) sacc[mf][nf][j] = 0.0f;

#pragma unroll
        for (int ks = 0; ks < 8; ks++) {
            uint32_t a[2][4];
#pragma unroll
            for (int mf = 0; mf < 2; mf++) {
                const float* qb = &Qs[(wm * 32 + mf * 16 + row) * QSTR + ks * 8 + col];
                a[mf][0] = __float_as_uint(qb[0]);
                a[mf][1] = __float_as_uint(qb[8 * QSTR]);
                a[mf][2] = __float_as_uint(qb[4]);
                a[mf][3] = __float_as_uint(qb[8 * QSTR + 4]);
            }
#pragma unroll
            for (int nf = 0; nf < 4; nf++) {
                const float* kb = &Ks[(wn * 32 + nf * 8 + row) * KSTR + ks * 8 + col];
                uint32_t bb[2];
                bb[0] = __float_as_uint(kb[0]);
                bb[1] = __float_as_uint(kb[4]);
                mma8(sacc[0][nf], a[0], bb);
                mma8(sacc[1][nf], a[1], bb);
            }
        }

        // ---- softmax (no max subtraction), tf32-round P, rowsum ----
#pragma unroll
        for (int mf = 0; mf < 2; mf++) {
            const int q0 = wm * 32 + mf * 16 + row;
#pragma unroll
            for (int nf = 0; nf < 4; nf++) {
                float p0 = to_tf32(__expf(sacc[mf][nf][0]));
                float p1 = to_tf32(__expf(sacc[mf][nf][1]));
                float p2 = to_tf32(__expf(sacc[mf][nf][2]));
                float p3 = to_tf32(__expf(sacc[mf][nf][3]));
                lsum[mf][0] += p0 + p1;
                lsum[mf][1] += p2 + p3;
                const int cbase = wn * 32 + nf * 8 + 2 * col;
                *reinterpret_cast<float2*>(&Ps[q0 * PSTR2 + cbase]) = make_float2(p0, p1);
                *reinterpret_cast<float2*>(&Ps[(q0 + 8) * PSTR2 + cbase]) = make_float2(p2, p3);
            }
        }
        __syncthreads();   // #1: Ps ready; all S reads of Ks done

        // Issue chunk ci+1 copies: K into the (now idle) single K buffer,
        // V into the other V buffer. Lands under PV + next-chunk wait.
        if (ci + 1 < NCH) {
            const size_t s1 = (size_t)(ci + 1) * BN;
            const uint32_t vd = OFF_V + (cur ^ 1) * VBUF;
#pragma unroll
            for (int it = 0; it < 4; it++) {
                int r = rb + 32 * it;
                cp16(sb + (uint32_t)(OFF_K + r * KSTR + cc) * 4,
                     &Kg[base + (s1 + r) * HDIM + cc]);
                cp16(sb + (vd + r * VSTR + cc) * 4,
                     &Vg[base + (s1 + r) * HDIM + cc]);
            }
            CP_COMMIT();
        }

        // ---- O += P V : M128 N64 K128, warp tile 32x16 ----
#pragma unroll
        for (int ks = 0; ks < 16; ks++) {
            uint32_t a[2][4];
#pragma unroll
            for (int mf = 0; mf < 2; mf++) {
                const float* pb = &Ps[(wm * 32 + mf * 16 + row) * PSTR2 + ks * 8 + col];
                a[mf][0] = __float_as_uint(pb[0]);
                a[mf][1] = __float_as_uint(pb[8 * PSTR2]);
                a[mf][2] = __float_as_uint(pb[4]);
                a[mf][3] = __float_as_uint(pb[8 * PSTR2 + 4]);
            }
#pragma unroll
            for (int nf = 0; nf < 2; nf++) {
                const float* vb = &Vs[(ks * 8 + col) * VSTR + wn * 16 + nf * 8 + row];
                uint32_t bb[2];
                bb[0] = __float_as_uint(vb[0]);
                bb[1] = __float_as_uint(vb[4 * VSTR]);
                mma8(oacc[0][nf], a[0], bb);
                mma8(oacc[1][nf], a[1], bb);
            }
        }
    }

    // ---- cross-warp rowsum combine (4 n-slices) ----
#pragma unroll
    for (int mf = 0; mf < 2; mf++)
#pragma unroll
        for (int i = 0; i < 2; i++) {
            float l = lsum[mf][i];
            l += __shfl_xor_sync(0xffffffffu, l, 1);
            l += __shfl_xor_sync(0xffffffffu, l, 2);
            if (col == 0)
                ls[wn * 128 + wm * 32 + mf * 16 + 8 * i + row] = l;
        }
    __syncthreads();

    // ---- epilogue: out = O / l ----
#pragma unroll
    for (int mf = 0; mf < 2; mf++) {
#pragma unroll
        for (int i = 0; i < 2; i++) {
            const int q = wm * 32 + mf * 16 + 8 * i + row;
            const float inv = 1.0f / (ls[q] + ls[128 + q] + ls[256 + q] + ls[384 + q]);
            float* dst = out + base + (size_t)(t0 + q) * HDIM;
#pragma unroll
            for (int nf = 0; nf < 2; nf++) {
                const int d = wn * 16 + nf * 8 + 2 * col;
                *reinterpret_cast<float2*>(&dst[d]) =
                    make_float2(oacc[mf][nf][2 * i] * inv, oacc[mf][nf][2 * i + 1] * inv);
            }
        }
    }
}

// ---------------------------------------------------------------------------
extern "C" void kernel_launch(void* const* d_in, const int* in_sizes, int n_in,
                              void* d_out, int out_size) {
    const float* x  = (const float*)d_in[0];
    const float* wq = (const float*)d_in[1];
    const float* wk = (const float*)d_in[2];
    const float* wv = (const float*)d_in[3];
    float* out = (float*)d_out;
    (void)in_sizes; (void)n_in; (void)out_size;

    cudaFuncSetAttribute(proj_mma_kernel,
                         cudaFuncAttributeMaxDynamicSharedMemorySize, PROJ_SMEM);
    proj_mma_kernel<<<MTOT / 128, 256, PROJ_SMEM>>>(x, wq, wk, wv);

    cudaFuncSetAttribute(attn_mma_kernel,
                         cudaFuncAttributeMaxDynamicSharedMemorySize, ATTN_SMEM);
    dim3 agrid(TT / BM, BB);
    attn_mma_kernel<<<agrid, 512, ATTN_SMEM>>>(out);
}

// round 12
// speedup vs baseline: 1.0493x; 1.0493x over previous
#include <cuda_runtime.h>
#include <cstdint>

// Problem constants
#define BB 4
#define TT 4096
#define DD 1024
#define HDIM 64
#define MTOT (BB*TT)   // 16384 rows

// Scratch: Q, K, V row-major [b*T, 64]; Q pre-scaled by 1/8; all tf32-rounded.
__device__ float g_QKV[3][(size_t)MTOT * HDIM];

// ---------------------------- helpers --------------------------------------
__device__ __forceinline__ float to_tf32(float x) {
    uint32_t u;
    asm("cvt.rna.tf32.f32 %0, %1;" : "=r"(u) : "f"(x));
    return __uint_as_float(u);
}

__device__ __forceinline__ uint32_t smem_u32(const void* p) {
    uint32_t a;
    asm("{ .reg .u64 t; cvta.to.shared.u64 t, %1; cvt.u32.u64 %0, t; }"
        : "=r"(a) : "l"(p));
    return a;
}

// cp.async 16B, L2-cached (cg). sm_80+ -> safe on the sm_103 family target.
__device__ __forceinline__ void cp16(uint32_t dst, const void* src) {
    asm volatile("cp.async.cg.shared.global [%0], [%1], 16;"
                 :: "r"(dst), "l"(src) : "memory");
}
#define CP_COMMIT() asm volatile("cp.async.commit_group;" ::: "memory")
#define CP_WAIT0()  asm volatile("cp.async.wait_group 0;" ::: "memory")

// m16n8k8 tf32 mma, D += A*B (accumulate in place)
__device__ __forceinline__ void mma8(float* d, const uint32_t* a, const uint32_t* b) {
    asm volatile(
        "mma.sync.aligned.m16n8k8.row.col.f32.tf32.tf32.f32 "
        "{%0,%1,%2,%3}, {%4,%5,%6,%7}, {%8,%9}, {%0,%1,%2,%3};"
        : "+f"(d[0]), "+f"(d[1]), "+f"(d[2]), "+f"(d[3])
        : "r"(a[0]), "r"(a[1]), "r"(a[2]), "r"(a[3]), "r"(b[0]), "r"(b[1]));
}

// ---------------------------------------------------------------------------
// Projection via tensor cores (unchanged from R6): out[m,0:192] = x @ [wq|wk|wv]^T
// ---------------------------------------------------------------------------
#define PKC 32
#define PSTRIDE 36
#define PXSZ (128 * PSTRIDE)
#define PWSZ (192 * PSTRIDE)
#define PBUF (PXSZ + PWSZ)
#define PROJ_SMEM (2 * PBUF * 4)         // 92160 bytes

__global__ __launch_bounds__(256, 1) void proj_mma_kernel(
    const float* __restrict__ x,
    const float* __restrict__ wq,
    const float* __restrict__ wk,
    const float* __restrict__ wv)
{
    extern __shared__ __align__(16) float psm[];

    const int tid  = threadIdx.x;
    const int wid  = tid >> 5;
    const int lane = tid & 31;
    const int wm   = wid >> 1;
    const int wn   = wid & 1;
    const int row  = lane >> 2;
    const int col  = lane & 3;
    const int m0   = blockIdx.x * 128;

    const float* xsrc[4];
    const float* wsrc[6];
    int xdst[4], wdst[6];
#pragma unroll
    for (int i = 0; i < 4; i++) {
        int idx = tid + i * 256;
        int r = idx >> 3, q = idx & 7;
        xsrc[i] = &x[(size_t)(m0 + r) * DD + q * 4];
        xdst[i] = r * PSTRIDE + q * 4;
    }
#pragma unroll
    for (int i = 0; i < 6; i++) {
        int idx = tid + i * 256;
        int r = idx >> 3, q = idx & 7;
        const float* wbase = (r < 64) ? &wq[(size_t)r * DD]
                           : (r < 128) ? &wk[(size_t)(r - 64) * DD]
                                       : &wv[(size_t)(r - 128) * DD];
        wsrc[i] = wbase + q * 4;
        wdst[i] = r * PSTRIDE + q * 4;
    }

    float acc[2][12][4];
#pragma unroll
    for (int mf = 0; mf < 2; mf++)
#pragma unroll
        for (int nf = 0; nf < 12; nf++)
#pragma unroll
            for (int j = 0; j < 4; j++) acc[mf][nf][j] = 0.0f;

    float4 xr[4], wr[6];
#pragma unroll
    for (int i = 0; i < 4; i++) xr[i] = *reinterpret_cast<const float4*>(xsrc[i]);
#pragma unroll
    for (int i = 0; i < 6; i++) wr[i] = *reinterpret_cast<const float4*>(wsrc[i]);

    for (int ci = 0; ci < DD / PKC; ci++) {
        float* Xb = psm + (ci & 1) * PBUF;
        float* Wb = Xb + PXSZ;

#pragma unroll
        for (int i = 0; i < 4; i++) {
            float4 v = xr[i];
            float4 t = make_float4(to_tf32(v.x), to_tf32(v.y), to_tf32(v.z), to_tf32(v.w));
            *reinterpret_cast<float4*>(&Xb[xdst[i]]) = t;
        }
#pragma unroll
        for (int i = 0; i < 6; i++) {
            float4 v = wr[i];
            float4 t = make_float4(to_tf32(v.x), to_tf32(v.y), to_tf32(v.z), to_tf32(v.w));
            *reinterpret_cast<float4*>(&Wb[wdst[i]]) = t;
        }
        __syncthreads();

        if (ci + 1 < DD / PKC) {
            const int kb = (ci + 1) * PKC;
#pragma unroll
            for (int i = 0; i < 4; i++)
                xr[i] = *reinterpret_cast<const float4*>(xsrc[i] + kb);
#pragma unroll
            for (int i = 0; i < 6; i++)
                wr[i] = *reinterpret_cast<const float4*>(wsrc[i] + kb);
        }

#pragma unroll
        for (int ks = 0; ks < 4; ks++) {
            uint32_t a[2][4];
#pragma unroll
            for (int mf = 0; mf < 2; mf++) {
                const float* ab = &Xb[(wm * 32 + mf * 16 + row) * PSTRIDE + ks * 8 + col];
                a[mf][0] = __float_as_uint(ab[0]);
                a[mf][1] = __float_as_uint(ab[8 * PSTRIDE]);
                a[mf][2] = __float_as_uint(ab[4]);
                a[mf][3] = __float_as_uint(ab[8 * PSTRIDE + 4]);
            }
#pragma unroll
            for (int nf = 0; nf < 12; nf++) {
                const float* bbp = &Wb[(wn * 96 + nf * 8 + row) * PSTRIDE + ks * 8 + col];
                uint32_t bb[2];
                bb[0] = __float_as_uint(bbp[0]);
                bb[1] = __float_as_uint(bbp[4]);
                mma8(acc[0][nf], a[0], bb);
                mma8(acc[1][nf], a[1], bb);
            }
        }
    }

#pragma unroll
    for (int mf = 0; mf < 2; mf++) {
#pragma unroll
        for (int i = 0; i < 2; i++) {
            const int m = m0 + wm * 32 + mf * 16 + 8 * i + row;
#pragma unroll
            for (int nf = 0; nf < 12; nf++) {
                const int cg = wn * 96 + nf * 8 + 2 * col;
                const int which = cg >> 6;
                const int n = cg & 63;
                const float scale = (which == 0) ? 0.125f : 1.0f;
                float2 v = make_float2(to_tf32(acc[mf][nf][2 * i] * scale),
                                       to_tf32(acc[mf][nf][2 * i + 1] * scale));
                *reinterpret_cast<float2*>(&g_QKV[which][(size_t)m * HDIM + n]) = v;
            }
        }
    }
}

// ---------------------------------------------------------------------------
// Tensor-core attention: R9's proven structure and protocol, CTA shrunk to
// BM=64 x BN=64 with 128 threads / 4 warps so TWO independent CTAs co-reside
// per SM (89.6 KB smem each). Cross-CTA drift overlaps softmax MUFU with the
// other CTA's HMMA; per-warp tiles stay 32x32 so LDS-per-mma matches R9.
//
//   S  = Q K^T : warps 2(m) x 2(n), warp tile 32x32, frags 2(m) x 4(n), K=64
//   PV = P V   : warps 2(m) x 2(n), warp tile 32x32, frags 2(m) x 4(n), K=64
// K single-buffered (copies for ci+1 issued after sync #1), V double-buffered.
// smem (floats): Qs 64*68 | Ks 64*68 | Vs[2] 64*72 | Ps 64*68 | ls 2*64
// ---------------------------------------------------------------------------
#define BM 64
#define BN 64
#define NCH (TT / BN)
#define QSTR 68
#define KSTR 68
#define VSTR 72
#define PSTR2 68
#define VBUF (64 * VSTR)

#define OFF_Q  0
#define OFF_K  (OFF_Q + 64 * QSTR)             //  4352
#define OFF_V  (OFF_K + 64 * KSTR)             //  8704 (buf b at + b*VBUF)
#define OFF_P  (OFF_V + 2 * VBUF)              // 17920
#define OFF_L  (OFF_P + 64 * PSTR2)            // 22272
#define ATTN_SMEM ((OFF_L + 128) * 4)          // 89600 bytes

__global__ __launch_bounds__(128, 2) void attn_mma_kernel(float* __restrict__ out)
{
    extern __shared__ __align__(16) float sm[];
    float* Qs = sm + OFF_Q;
    float* Ps = sm + OFF_P;
    float* ls = sm + OFF_L;
    const uint32_t sb = smem_u32(sm);

    const int tid  = threadIdx.x;
    const int wid  = tid >> 5;
    const int lane = tid & 31;
    const int wm   = wid >> 1;          // 0..1 : 32-row group
    const int wn   = wid & 1;           // 0..1 : n-half
    const int row  = lane >> 2;         // 0..7
    const int col  = lane & 3;          // 0..3

    const int b  = blockIdx.y;
    const int t0 = blockIdx.x * BM;
    const float* Q  = g_QKV[0];
    const float* Kg = g_QKV[1];
    const float* Vg = g_QKV[2];
    const size_t base = (size_t)b * TT * HDIM;

    // Staging geometry: 128 threads; rb = tid>>4 (0..7), cc fixed; rows rb+8*it.
    const int rb = tid >> 4;
    const int cc = (tid & 15) << 2;

    // Load Q tile once (plain LDG/STS): 64 x 64, 4 float4 per thread... (8 its of 64 rows)
#pragma unroll
    for (int it = 0; it < 8; it++) {
        int r = rb + 8 * it;
        float4 v = *reinterpret_cast<const float4*>(&Q[base + (size_t)(t0 + r) * HDIM + cc]);
        *reinterpret_cast<float4*>(&Qs[r * QSTR + cc]) = v;
    }

    // Issue chunk 0 K/V copies (K -> single buffer, V -> buffer 0).
#pragma unroll
    for (int it = 0; it < 8; it++) {
        int r = rb + 8 * it;
        cp16(sb + (uint32_t)(OFF_K + r * KSTR + cc) * 4, &Kg[base + (size_t)r * HDIM + cc]);
        cp16(sb + (uint32_t)(OFF_V + r * VSTR + cc) * 4, &Vg[base + (size_t)r * HDIM + cc]);
    }
    CP_COMMIT();

    float oacc[2][4][4];
    float lsum[2][2];
#pragma unroll
    for (int mf = 0; mf < 2; mf++) {
        lsum[mf][0] = 0.0f; lsum[mf][1] = 0.0f;
#pragma unroll
        for (int nf = 0; nf < 4; nf++)
#pragma unroll
            for (int j = 0; j < 4; j++) oacc[mf][nf][j] = 0.0f;
    }

    for (int ci = 0; ci < NCH; ci++) {
        const int cur = ci & 1;
        const float* Ks = sm + OFF_K;
        const float* Vs = sm + OFF_V + cur * VBUF;

        CP_WAIT0();
        __syncthreads();   // chunk ci K/V resident & visible; PV(ci-1) reads done

        // ---- S = Q K^T : M64 N64 K64, warp tile 32x32 ----
        float sacc[2][4][4];
#pragma unroll
        for (int mf = 0; mf < 2; mf++)
#pragma unroll
            for (int nf = 0; nf < 4; nf++)
#pragma unroll
                for (int j = 0; j < 4; j++) sacc[mf][nf][j] = 0.0f;

#pragma unroll
        for (int ks = 0; ks < 8; ks++) {
            uint32_t a[2][4];
#pragma unroll
            for (int mf = 0; mf < 2; mf++) {
                const float* qb = &Qs[(wm * 32 + mf * 16 + row) * QSTR + ks * 8 + col];
                a[mf][0] = __float_as_uint(qb[0]);
                a[mf][1] = __float_as_uint(qb[8 * QSTR]);
                a[mf][2] = __float_as_uint(qb[4]);
                a[mf][3] = __float_as_uint(qb[8 * QSTR + 4]);
            }
#pragma unroll
            for (int nf = 0; nf < 4; nf++) {
                const float* kb = &Ks[(wn * 32 + nf * 8 + row) * KSTR + ks * 8 + col];
                uint32_t bb[2];
                bb[0] = __float_as_uint(kb[0]);
                bb[1] = __float_as_uint(kb[4]);
                mma8(sacc[0][nf], a[0], bb);
                mma8(sacc[1][nf], a[1], bb);
            }
        }

        // ---- softmax (no max subtraction), tf32-round P, rowsum ----
#pragma unroll
        for (int mf = 0; mf < 2; mf++) {
            const int q0 = wm * 32 + mf * 16 + row;
#pragma unroll
            for (int nf = 0; nf < 4; nf++) {
                float p0 = to_tf32(__expf(sacc[mf][nf][0]));
                float p1 = to_tf32(__expf(sacc[mf][nf][1]));
                float p2 = to_tf32(__expf(sacc[mf][nf][2]));
                float p3 = to_tf32(__expf(sacc[mf][nf][3]));
                lsum[mf][0] += p0 + p1;
                lsum[mf][1] += p2 + p3;
                const int cbase = wn * 32 + nf * 8 + 2 * col;
                *reinterpret_cast<float2*>(&Ps[q0 * PSTR2 + cbase]) = make_float2(p0, p1);
                *reinterpret_cast<float2*>(&Ps[(q0 + 8) * PSTR2 + cbase]) = make_float2(p2, p3);
            }
        }
        __syncthreads();   // #1: Ps ready; all S reads of Ks done

        // Issue chunk ci+1 copies: K into the (now idle) single K buffer,
        // V into the other V buffer. Lands under PV + next-chunk wait.
        if (ci + 1 < NCH) {
            const size_t s1 = (size_t)(ci + 1) * BN;
            const uint32_t vd = OFF_V + (cur ^ 1) * VBUF;
#pragma unroll
            for (int it = 0; it < 8; it++) {
                int r = rb + 8 * it;
                cp16(sb + (uint32_t)(OFF_K + r * KSTR + cc) * 4,
                     &Kg[base + (s1 + r) * HDIM + cc]);
                cp16(sb + (vd + r * VSTR + cc) * 4,
                     &Vg[base + (s1 + r) * HDIM + cc]);
            }
            CP_COMMIT();
        }

        // ---- O += P V : M64 N64 K64, warp tile 32x32 ----
#pragma unroll
        for (int ks = 0; ks < 8; ks++) {
            uint32_t a[2][4];
#pragma unroll
            for (int mf = 0; mf < 2; mf++) {
                const float* pb = &Ps[(wm * 32 + mf * 16 + row) * PSTR2 + ks * 8 + col];
                a[mf][0] = __float_as_uint(pb[0]);
                a[mf][1] = __float_as_uint(pb[8 * PSTR2]);
                a[mf][2] = __float_as_uint(pb[4]);
                a[mf][3] = __float_as_uint(pb[8 * PSTR2 + 4]);
            }
#pragma unroll
            for (int nf = 0; nf < 4; nf++) {
                const float* vb = &Vs[(ks * 8 + col) * VSTR + wn * 32 + nf * 8 + row];
                uint32_t bb[2];
                bb[0] = __float_as_uint(vb[0]);
                bb[1] = __float_as_uint(vb[4 * VSTR]);
                mma8(oacc[0][nf], a[0], bb);
                mma8(oacc[1][nf], a[1], bb);
            }
        }
    }

    // ---- cross-warp rowsum combine ----
#pragma unroll
    for (int mf = 0; mf < 2; mf++)
#pragma unroll
        for (int i = 0; i < 2; i++) {
            float l = lsum[mf][i];
            l += __shfl_xor_sync(0xffffffffu, l, 1);
            l += __shfl_xor_sync(0xffffffffu, l, 2);
            if (col == 0)
                ls[wn * 64 + wm * 32 + mf * 16 + 8 * i + row] = l;
        }
    __syncthreads();

    // ---- epilogue: out = O / l ----
#pragma unroll
    for (int mf = 0; mf < 2; mf++) {
#pragma unroll
        for (int i = 0; i < 2; i++) {
            const int q = wm * 32 + mf * 16 + 8 * i + row;
            const float inv = 1.0f / (ls[q] + ls[64 + q]);
            float* dst = out + base + (size_t)(t0 + q) * HDIM;
#pragma unroll
            for (int nf = 0; nf < 4; nf++) {
                const int d = wn * 32 + nf * 8 + 2 * col;
                *reinterpret_cast<float2*>(&dst[d]) =
                    make_float2(oacc[mf][nf][2 * i] * inv, oacc[mf][nf][2 * i + 1] * inv);
            }
        }
    }
}

// ---------------------------------------------------------------------------
extern "C" void kernel_launch(void* const* d_in, const int* in_sizes, int n_in,
                              void* d_out, int out_size) {
    const float* x  = (const float*)d_in[0];
    const float* wq = (const float*)d_in[1];
    const float* wk = (const float*)d_in[2];
    const float* wv = (const float*)d_in[3];
    float* out = (float*)d_out;
    (void)in_sizes; (void)n_in; (void)out_size;

    cudaFuncSetAttribute(proj_mma_kernel,
                         cudaFuncAttributeMaxDynamicSharedMemorySize, PROJ_SMEM);
    proj_mma_kernel<<<MTOT / 128, 256, PROJ_SMEM>>>(x, wq, wk, wv);

    cudaFuncSetAttribute(attn_mma_kernel,
                         cudaFuncAttributeMaxDynamicSharedMemorySize, ATTN_SMEM);
    dim3 agrid(TT / BM, BB);
    attn_mma_kernel<<<agrid, 128, ATTN_SMEM>>>(out);
}

// round 16
// speedup vs baseline: 1.1730x; 1.1178x over previous
#include <cuda_runtime.h>
#include <cstdint>

// Problem constants
#define BB 4
#define TT 4096
#define DD 1024
#define HDIM 64
#define MTOT (BB*TT)   // 16384 rows

// Scratch: Q, K, V row-major [b*T, 64]; Q pre-scaled by 1/8; all tf32-rounded.
__device__ float g_QKV[3][(size_t)MTOT * HDIM];

// ---------------------------- helpers --------------------------------------
__device__ __forceinline__ float to_tf32(float x) {
    uint32_t u;
    asm("cvt.rna.tf32.f32 %0, %1;" : "=r"(u) : "f"(x));
    return __uint_as_float(u);
}

__device__ __forceinline__ uint32_t smem_u32(const void* p) {
    uint32_t a;
    asm("{ .reg .u64 t; cvta.to.shared.u64 t, %1; cvt.u32.u64 %0, t; }"
        : "=r"(a) : "l"(p));
    return a;
}

// cp.async 16B, L2-cached (cg). sm_80+ -> safe on the sm_103 family target.
__device__ __forceinline__ void cp16(uint32_t dst, const void* src) {
    asm volatile("cp.async.cg.shared.global [%0], [%1], 16;"
                 :: "r"(dst), "l"(src) : "memory");
}
#define CP_COMMIT() asm volatile("cp.async.commit_group;" ::: "memory")
#define CP_WAIT0()  asm volatile("cp.async.wait_group 0;" ::: "memory")

// m16n8k8 tf32 mma, D += A*B (accumulate in place)
__device__ __forceinline__ void mma8(float* d, const uint32_t* a, const uint32_t* b) {
    asm volatile(
        "mma.sync.aligned.m16n8k8.row.col.f32.tf32.tf32.f32 "
        "{%0,%1,%2,%3}, {%4,%5,%6,%7}, {%8,%9}, {%0,%1,%2,%3};"
        : "+f"(d[0]), "+f"(d[1]), "+f"(d[2]), "+f"(d[3])
        : "r"(a[0]), "r"(a[1]), "r"(a[2]), "r"(a[3]), "r"(b[0]), "r"(b[1]));
}

// ---------------------------------------------------------------------------
// Projection via tensor cores (unchanged from R6): out[m,0:192] = x @ [wq|wk|wv]^T
// ---------------------------------------------------------------------------
#define PKC 32
#define PSTRIDE 36
#define PXSZ (128 * PSTRIDE)
#define PWSZ (192 * PSTRIDE)
#define PBUF (PXSZ + PWSZ)
#define PROJ_SMEM (2 * PBUF * 4)         // 92160 bytes

__global__ __launch_bounds__(256, 1) void proj_mma_kernel(
    const float* __restrict__ x,
    const float* __restrict__ wq,
    const float* __restrict__ wk,
    const float* __restrict__ wv)
{
    extern __shared__ __align__(16) float psm[];

    const int tid  = threadIdx.x;
    const int wid  = tid >> 5;
    const int lane = tid & 31;
    const int wm   = wid >> 1;
    const int wn   = wid & 1;
    const int row  = lane >> 2;
    const int col  = lane & 3;
    const int m0   = blockIdx.x * 128;

    const float* xsrc[4];
    const float* wsrc[6];
    int xdst[4], wdst[6];
#pragma unroll
    for (int i = 0; i < 4; i++) {
        int idx = tid + i * 256;
        int r = idx >> 3, q = idx & 7;
        xsrc[i] = &x[(size_t)(m0 + r) * DD + q * 4];
        xdst[i] = r * PSTRIDE + q * 4;
    }
#pragma unroll
    for (int i = 0; i < 6; i++) {
        int idx = tid + i * 256;
        int r = idx >> 3, q = idx & 7;
        const float* wbase = (r < 64) ? &wq[(size_t)r * DD]
                           : (r < 128) ? &wk[(size_t)(r - 64) * DD]
                                       : &wv[(size_t)(r - 128) * DD];
        wsrc[i] = wbase + q * 4;
        wdst[i] = r * PSTRIDE + q * 4;
    }

    float acc[2][12][4];
#pragma unroll
    for (int mf = 0; mf < 2; mf++)
#pragma unroll
        for (int nf = 0; nf < 12; nf++)
#pragma unroll
            for (int j = 0; j < 4; j++) acc[mf][nf][j] = 0.0f;

    float4 xr[4], wr[6];
#pragma unroll
    for (int i = 0; i < 4; i++) xr[i] = *reinterpret_cast<const float4*>(xsrc[i]);
#pragma unroll
    for (int i = 0; i < 6; i++) wr[i] = *reinterpret_cast<const float4*>(wsrc[i]);

    for (int ci = 0; ci < DD / PKC; ci++) {
        float* Xb = psm + (ci & 1) * PBUF;
        float* Wb = Xb + PXSZ;

#pragma unroll
        for (int i = 0; i < 4; i++) {
            float4 v = xr[i];
            float4 t = make_float4(to_tf32(v.x), to_tf32(v.y), to_tf32(v.z), to_tf32(v.w));
            *reinterpret_cast<float4*>(&Xb[xdst[i]]) = t;
        }
#pragma unroll
        for (int i = 0; i < 6; i++) {
            float4 v = wr[i];
            float4 t = make_float4(to_tf32(v.x), to_tf32(v.y), to_tf32(v.z), to_tf32(v.w));
            *reinterpret_cast<float4*>(&Wb[wdst[i]]) = t;
        }
        __syncthreads();

        if (ci + 1 < DD / PKC) {
            const int kb = (ci + 1) * PKC;
#pragma unroll
            for (int i = 0; i < 4; i++)
                xr[i] = *reinterpret_cast<const float4*>(xsrc[i] + kb);
#pragma unroll
            for (int i = 0; i < 6; i++)
                wr[i] = *reinterpret_cast<const float4*>(wsrc[i] + kb);
        }

#pragma unroll
        for (int ks = 0; ks < 4; ks++) {
            uint32_t a[2][4];
#pragma unroll
            for (int mf = 0; mf < 2; mf++) {
                const float* ab = &Xb[(wm * 32 + mf * 16 + row) * PSTRIDE + ks * 8 + col];
                a[mf][0] = __float_as_uint(ab[0]);
                a[mf][1] = __float_as_uint(ab[8 * PSTRIDE]);
                a[mf][2] = __float_as_uint(ab[4]);
                a[mf][3] = __float_as_uint(ab[8 * PSTRIDE + 4]);
            }
#pragma unroll
            for (int nf = 0; nf < 12; nf++) {
                const float* bbp = &Wb[(wn * 96 + nf * 8 + row) * PSTRIDE + ks * 8 + col];
                uint32_t bb[2];
                bb[0] = __float_as_uint(bbp[0]);
                bb[1] = __float_as_uint(bbp[4]);
                mma8(acc[0][nf], a[0], bb);
                mma8(acc[1][nf], a[1], bb);
            }
        }
    }

#pragma unroll
    for (int mf = 0; mf < 2; mf++) {
#pragma unroll
        for (int i = 0; i < 2; i++) {
            const int m = m0 + wm * 32 + mf * 16 + 8 * i + row;
#pragma unroll
            for (int nf = 0; nf < 12; nf++) {
                const int cg = wn * 96 + nf * 8 + 2 * col;
                const int which = cg >> 6;
                const int n = cg & 63;
                const float scale = (which == 0) ? 0.125f : 1.0f;
                float2 v = make_float2(to_tf32(acc[mf][nf][2 * i] * scale),
                                       to_tf32(acc[mf][nf][2 * i + 1] * scale));
                *reinterpret_cast<float2*>(&g_QKV[which][(size_t)m * HDIM + n]) = v;
            }
        }
    }
}

// ---------------------------------------------------------------------------
// Tensor-core attention, register-resident P (no smem P, no softmax barrier).
// Each warp owns 32 query rows (wm) x 64 keys (wn); after S + exp (registers),
// the C-fragments are repacked to A-fragments via shfl and PV accumulates a
// PARTIAL O over the warp's own 64 keys. wn=0/1 partials are summed once in
// the epilogue (valid because no-max softmax makes O accumulation linear).
// K and V both double-buffered via cp.async; ONE barrier per chunk.
//
//   S  = Q K^T : warps 4(m) x 2(n), warp tile 32x64, frags 2(m) x 8(n), K=64
//   PV partial : A = P(reg) 32x64, B = V slice, out 32x64: 2(m) x 8(d), K=64
// smem (floats): Qs 128*68 | Ks[2] 128*68 | Vs[2] 128*72 | ls 2*128
//   total 44800 floats = 179200 bytes. Epilogue reuses Vs area as O scratch.
// ---------------------------------------------------------------------------
#define BM 128
#define BN 128
#define NCH (TT / BN)
#define QSTR 68
#define KSTR 68
#define VSTR 72
#define KBUF (128 * KSTR)
#define VBUF (128 * VSTR)
#define OSTR 66

#define OFF_Q  0
#define OFF_K  (OFF_Q + 128 * QSTR)            //  8704 (buf b at + b*KBUF)
#define OFF_V  (OFF_K + 2 * KBUF)              // 26112 (buf b at + b*VBUF)
#define OFF_L  (OFF_V + 2 * VBUF)              // 44544
#define ATTN_SMEM ((OFF_L + 256) * 4)          // 179200 bytes

__global__ __launch_bounds__(256, 1) void attn_mma_kernel(float* __restrict__ out)
{
    extern __shared__ __align__(16) float sm[];
    float* Qs = sm + OFF_Q;
    float* ls = sm + OFF_L;
    float* Os = sm + OFF_V;            // epilogue scratch (Vs dead by then)
    const uint32_t sb = smem_u32(sm);

    const int tid  = threadIdx.x;
    const int wid  = tid >> 5;
    const int lane = tid & 31;
    const int wm   = wid >> 1;          // 0..3 : 32-row query group
    const int wn   = wid & 1;           // 0..1 : 64-key half
    const int row  = lane >> 2;         // 0..7
    const int col  = lane & 3;          // 0..3

    const int b  = blockIdx.y;
    const int t0 = blockIdx.x * BM;
    const float* Q  = g_QKV[0];
    const float* Kg = g_QKV[1];
    const float* Vg = g_QKV[2];
    const size_t base = (size_t)b * TT * HDIM;

    // Staging geometry: rb = tid>>4 (0..15), cc fixed; rows rb + 16*it.
    const int rb = tid >> 4;
    const int cc = (tid & 15) << 2;

    // Load Q tile once (plain LDG/STS): 128 x 64, 8 float4 per thread.
#pragma unroll
    for (int it = 0; it < 8; it++) {
        int r = rb + 16 * it;
        float4 v = *reinterpret_cast<const float4*>(&Q[base + (size_t)(t0 + r) * HDIM + cc]);
        *reinterpret_cast<float4*>(&Qs[r * QSTR + cc]) = v;
    }

    // Issue chunk 0 K/V copies into buffer 0.
#pragma unroll
    for (int it = 0; it < 8; it++) {
        int r = rb + 16 * it;
        cp16(sb + (uint32_t)(OFF_K + r * KSTR + cc) * 4, &Kg[base + (size_t)r * HDIM + cc]);
        cp16(sb + (uint32_t)(OFF_V + r * VSTR + cc) * 4, &Vg[base + (size_t)r * HDIM + cc]);
    }
    CP_COMMIT();

    float oacc[2][8][4];               // partial O: 32 rows x 64 d (this warp's keys)
    float lsum[2][2];
#pragma unroll
    for (int mf = 0; mf < 2; mf++) {
        lsum[mf][0] = 0.0f; lsum[mf][1] = 0.0f;
#pragma unroll
        for (int nf = 0; nf < 8; nf++)
#pragma unroll
            for (int j = 0; j < 4; j++) oacc[mf][nf][j] = 0.0f;
    }

    const int s0lane = (lane & 28) | (col >> 1);   // repack source lanes
    const int s1lane = s0lane + 2;
    const bool oddt  = (col & 1);

    for (int ci = 0; ci < NCH; ci++) {
        const int cur = ci & 1;
        const float* Ks = sm + OFF_K + cur * KBUF;
        const float* Vs = sm + OFF_V + cur * VBUF;

        CP_WAIT0();
        __syncthreads();   // chunk ci K/V resident & visible; all reads of buf cur^1 done

        // Issue chunk ci+1 copies into the other buffers (land under S+PV).
        if (ci + 1 < NCH) {
            const size_t s1 = (size_t)(ci + 1) * BN;
            const uint32_t kd = OFF_K + (cur ^ 1) * KBUF;
            const uint32_t vd = OFF_V + (cur ^ 1) * VBUF;
#pragma unroll
            for (int it = 0; it < 8; it++) {
                int r = rb + 16 * it;
                cp16(sb + (kd + r * KSTR + cc) * 4, &Kg[base + (s1 + r) * HDIM + cc]);
                cp16(sb + (vd + r * VSTR + cc) * 4, &Vg[base + (s1 + r) * HDIM + cc]);
            }
            CP_COMMIT();
        }

        // ---- S = Q K^T : warp tile 32 x 64 (keys wn*64..wn*64+63) ----
        float sacc[2][8][4];
#pragma unroll
        for (int mf = 0; mf < 2; mf++)
#pragma unroll
            for (int nf = 0; nf < 8; nf++)
#pragma unroll
                for (int j = 0; j < 4; j++) sacc[mf][nf][j] = 0.0f;

#pragma unroll
        for (int ks = 0; ks < 8; ks++) {
            uint32_t a[2][4];
#pragma unroll
            for (int mf = 0; mf < 2; mf++) {
                const float* qb = &Qs[(wm * 32 + mf * 16 + row) * QSTR + ks * 8 + col];
                a[mf][0] = __float_as_uint(qb[0]);
                a[mf][1] = __float_as_uint(qb[8 * QSTR]);
                a[mf][2] = __float_as_uint(qb[4]);
                a[mf][3] = __float_as_uint(qb[8 * QSTR + 4]);
            }
#pragma unroll
            for (int nf = 0; nf < 8; nf++) {
                const float* kb = &Ks[(wn * 64 + nf * 8 + row) * KSTR + ks * 8 + col];
                uint32_t bb[2];
                bb[0] = __float_as_uint(kb[0]);
                bb[1] = __float_as_uint(kb[4]);
                mma8(sacc[0][nf], a[0], bb);
                mma8(sacc[1][nf], a[1], bb);
            }
        }

        // ---- softmax in registers: P = tf32(exp(S)); rowsum ----
#pragma unroll
        for (int mf = 0; mf < 2; mf++) {
#pragma unroll
            for (int nf = 0; nf < 8; nf++) {
                float p0 = to_tf32(__expf(sacc[mf][nf][0]));
                float p1 = to_tf32(__expf(sacc[mf][nf][1]));
                float p2 = to_tf32(__expf(sacc[mf][nf][2]));
                float p3 = to_tf32(__expf(sacc[mf][nf][3]));
                lsum[mf][0] += p0 + p1;
                lsum[mf][1] += p2 + p3;
                sacc[mf][nf][0] = p0; sacc[mf][nf][1] = p1;
                sacc[mf][nf][2] = p2; sacc[mf][nf][3] = p3;
            }
        }

        // ---- PV partial: O += P(reg) * V[warp's keys] ----
        // Repack C-frag -> A-frag: A(q, key=ks*8+t) from C(q, key=2t'+par):
        //   src lane 4r+(t>>1) (+2 for t+4), register parity t&1.
#pragma unroll
        for (int ks = 0; ks < 8; ks++) {
            uint32_t a[2][4];
#pragma unroll
            for (int mf = 0; mf < 2; mf++) {
                float v00 = __shfl_sync(0xffffffffu, sacc[mf][ks][0], s0lane);
                float v01 = __shfl_sync(0xffffffffu, sacc[mf][ks][1], s0lane);
                float v02 = __shfl_sync(0xffffffffu, sacc[mf][ks][2], s0lane);
                float v03 = __shfl_sync(0xffffffffu, sacc[mf][ks][3], s0lane);
                float v10 = __shfl_sync(0xffffffffu, sacc[mf][ks][0], s1lane);
                float v11 = __shfl_sync(0xffffffffu, sacc[mf][ks][1], s1lane);
                float v12 = __shfl_sync(0xffffffffu, sacc[mf][ks][2], s1lane);
                float v13 = __shfl_sync(0xffffffffu, sacc[mf][ks][3], s1lane);
                a[mf][0] = __float_as_uint(oddt ? v01 : v00);
                a[mf][1] = __float_as_uint(oddt ? v03 : v02);
                a[mf][2] = __float_as_uint(oddt ? v11 : v10);
                a[mf][3] = __float_as_uint(oddt ? v13 : v12);
            }
#pragma unroll
            for (int nf = 0; nf < 8; nf++) {
                const float* vb = &Vs[(wn * 64 + ks * 8 + col) * VSTR + nf * 8 + row];
                uint32_t bb[2];
                bb[0] = __float_as_uint(vb[0]);
                bb[1] = __float_as_uint(vb[4 * VSTR]);
                mma8(oacc[0][nf], a[0], bb);
                mma8(oacc[1][nf], a[1], bb);
            }
        }
    }

    // ---- epilogue: combine wn partials, divide by total rowsum ----
    __syncthreads();   // Vs buffers dead; reuse as O scratch

    // rowsum combine (each warp's lsum covers its 64 keys)
#pragma unroll
    for (int mf = 0; mf < 2; mf++)
#pragma unroll
        for (int i = 0; i < 2; i++) {
            float l = lsum[mf][i];
            l += __shfl_xor_sync(0xffffffffu, l, 1);
            l += __shfl_xor_sync(0xffffffffu, l, 2);
            if (col == 0)
                ls[wn * 128 + wm * 32 + mf * 16 + 8 * i + row] = l;
        }

    // wn=1 warps park their partial O in smem
    if (wn == 1) {
#pragma unroll
        for (int mf = 0; mf < 2; mf++)
#pragma unroll
            for (int i = 0; i < 2; i++) {
                const int q = wm * 32 + mf * 16 + 8 * i + row;
#pragma unroll
                for (int nf = 0; nf < 8; nf++) {
                    *reinterpret_cast<float2*>(&Os[q * OSTR + nf * 8 + 2 * col]) =
                        make_float2(oacc[mf][nf][2 * i], oacc[mf][nf][2 * i + 1]);
                }
            }
    }
    __syncthreads();

    if (wn == 0) {
#pragma unroll
        for (int mf = 0; mf < 2; mf++) {
#pragma unroll
            for (int i = 0; i < 2; i++) {
                const int q = wm * 32 + mf * 16 + 8 * i + row;
                const float inv = 1.0f / (ls[q] + ls[128 + q]);
                float* dst = out + base + (size_t)(t0 + q) * HDIM;
#pragma unroll
                for (int nf = 0; nf < 8; nf++) {
                    float2 o = *reinterpret_cast<const float2*>(&Os[q * OSTR + nf * 8 + 2 * col]);
                    *reinterpret_cast<float2*>(&dst[nf * 8 + 2 * col]) =
                        make_float2((oacc[mf][nf][2 * i] + o.x) * inv,
                                    (oacc[mf][nf][2 * i + 1] + o.y) * inv);
                }
            }
        }
    }
}

// ---------------------------------------------------------------------------
extern "C" void kernel_launch(void* const* d_in, const int* in_sizes, int n_in,
                              void* d_out, int out_size) {
    const float* x  = (const float*)d_in[0];
    const float* wq = (const float*)d_in[1];
    const float* wk = (const float*)d_in[2];
    const float* wv = (const float*)d_in[3];
    float* out = (float*)d_out;
    (void)in_sizes; (void)n_in; (void)out_size;

    cudaFuncSetAttribute(proj_mma_kernel,
                         cudaFuncAttributeMaxDynamicSharedMemorySize, PROJ_SMEM);
    proj_mma_kernel<<<MTOT / 128, 256, PROJ_SMEM>>>(x, wq, wk, wv);

    cudaFuncSetAttribute(attn_mma_kernel,
                         cudaFuncAttributeMaxDynamicSharedMemorySize, ATTN_SMEM);
    dim3 agrid(TT / BM, BB);
    attn_mma_kernel<<<agrid, 256, ATTN_SMEM>>>(out);
}